// round 1
// baseline (speedup 1.0000x reference)
#include <cuda_runtime.h>
#include <math.h>

#define RR      2336
#define CIN     4
#define COUT    16
#define NK      2
#define NTHREADS 256
#define NWARP   (NTHREADS / 32)
#define RPT     10          // ceil(2336 / 256)

// Transposed W: [k][i][o][r], r contiguous -> coalesced streaming loads
__device__ float g_Wt[NK * CIN * COUT * RR];

__global__ void wtrans_kernel(const float* __restrict__ W) {
    int idx = blockIdx.x * blockDim.x + threadIdx.x;
    const int total = NK * RR * CIN * COUT;
    if (idx >= total) return;
    // source layout: ((k*RR + r)*CIN + i)*COUT + o
    int o = idx & 15;
    int i = (idx >> 4) & 3;
    int r = (idx >> 6) % RR;
    int k = (idx >> 6) / RR;
    g_Wt[((k * CIN + i) * COUT + o) * RR + r] = W[idx];
}

// -------- block reduction helpers (deterministic tree reductions) --------

template <int N>
__device__ __forceinline__ void block_sum(float* v, float* red, int lane, int wid) {
#pragma unroll
    for (int n = 0; n < N; ++n) {
        float x = v[n];
#pragma unroll
        for (int off = 16; off > 0; off >>= 1)
            x += __shfl_xor_sync(0xffffffffu, x, off);
        v[n] = x;
    }
    __syncthreads();              // prior users of red are done
    if (lane == 0) {
#pragma unroll
        for (int n = 0; n < N; ++n) red[wid * N + n] = v[n];
    }
    __syncthreads();
#pragma unroll
    for (int n = 0; n < N; ++n) {
        float t = 0.f;
#pragma unroll
        for (int w = 0; w < NWARP; ++w) t += red[w * N + n];
        v[n] = t;                 // broadcast result to every thread
    }
}

__device__ __forceinline__ float block_max(float x, float* red, int lane, int wid) {
#pragma unroll
    for (int off = 16; off > 0; off >>= 1)
        x = fmaxf(x, __shfl_xor_sync(0xffffffffu, x, off));
    __syncthreads();
    if (lane == 0) red[wid] = x;
    __syncthreads();
    float m = red[0];
#pragma unroll
    for (int w = 1; w < NWARP; ++w) m = fmaxf(m, red[w]);
    return m;
}

__device__ __forceinline__ void squash16(const float* s, float* v) {
    float n = 0.f;
#pragma unroll
    for (int o = 0; o < COUT; ++o) n = fmaf(s[o], s[o], n);
    float f = sqrtf(n) / (1.f + n);     // == (n/(1+n)) / sqrt(n)
#pragma unroll
    for (int o = 0; o < COUT; ++o) v[o] = s[o] * f;
}

// -------- main kernel: one block handles batches (2*bid, 2*bid+1) --------

__global__ __launch_bounds__(NTHREADS, 1)
void caps_kernel(const float* __restrict__ u, float* __restrict__ out) {
    extern __shared__ float sm[];
    float* uji_s = sm;                 // [COUT][RR]  (batch 1), bank-conflict-free
    float* red   = sm + COUT * RR;     // [NWARP * 17]

    const int tid  = threadIdx.x;
    const int lane = tid & 31;
    const int wid  = tid >> 5;
    const int b0 = blockIdx.x * 2;
    const int b1 = b0 + 1;
    const float* u0p = u + (size_t)b0 * RR * CIN;
    const float* u1p = u + (size_t)b1 * RR * CIN;

    float cls0[NK], cls1[NK];

    for (int k = 0; k < NK; ++k) {
        const float* Wt = g_Wt + k * (CIN * COUT * RR);

        // ---------------- Phase A: stream W once, build u_ji for BOTH batches
        float uji_r[RPT][COUT];        // batch 0 u_ji, registers
        float ss1[COUT];               // batch 1 route-sum
#pragma unroll
        for (int o = 0; o < COUT; ++o) ss1[o] = 0.f;
#pragma unroll
        for (int j = 0; j < RPT; ++j)
#pragma unroll
            for (int o = 0; o < COUT; ++o) uji_r[j][o] = 0.f;

#pragma unroll
        for (int j = 0; j < RPT; ++j) {
            int r = tid + j * NTHREADS;
            if (r < RR) {
                float4 a0 = *(const float4*)(u0p + (size_t)r * CIN);
                float4 a1 = *(const float4*)(u1p + (size_t)r * CIN);
                float c0[CIN] = {a0.x, a0.y, a0.z, a0.w};
                float c1[CIN] = {a1.x, a1.y, a1.z, a1.w};
                float acc1[COUT];
#pragma unroll
                for (int o = 0; o < COUT; ++o) acc1[o] = 0.f;
#pragma unroll
                for (int i = 0; i < CIN; ++i) {
#pragma unroll
                    for (int o = 0; o < COUT; ++o) {
                        float w = Wt[(i * COUT + o) * RR + r];
                        uji_r[j][o] = fmaf(c0[i], w, uji_r[j][o]);
                        acc1[o]     = fmaf(c1[i], w, acc1[o]);
                    }
                }
#pragma unroll
                for (int o = 0; o < COUT; ++o) {
                    uji_s[o * RR + r] = acc1[o];
                    ss1[o] += acc1[o];
                }
            }
        }

        // ---------------- Routing for batch 0 (register u_ji)
        {
            float s[COUT], v[COUT];
#pragma unroll
            for (int o = 0; o < COUT; ++o) {
                float t = 0.f;
#pragma unroll
                for (int j = 0; j < RPT; ++j) t += uji_r[j][o];
                s[o] = t;
            }
            block_sum<COUT>(s, red, lane, wid);
#pragma unroll
            for (int o = 0; o < COUT; ++o) s[o] *= (1.f / RR);
            squash16(s, v);

            float blr[RPT];            // per-thread b-logits, registers
            for (int it = 0; it < 2; ++it) {
                float mloc = -1e30f;
#pragma unroll
                for (int j = 0; j < RPT; ++j) {
                    int r = tid + j * NTHREADS;
                    if (r < RR) {
                        float d = 0.f;
#pragma unroll
                        for (int o = 0; o < COUT; ++o)
                            d = fmaf(uji_r[j][o], v[o], d);
                        float nb = (it == 0) ? d : (blr[j] + d);
                        blr[j] = nb;
                        mloc = fmaxf(mloc, nb);
                    }
                }
                float m = block_max(mloc, red, lane, wid);

                float acc[COUT + 1];
#pragma unroll
                for (int o = 0; o <= COUT; ++o) acc[o] = 0.f;
#pragma unroll
                for (int j = 0; j < RPT; ++j) {
                    int r = tid + j * NTHREADS;
                    if (r < RR) {
                        float w = __expf(blr[j] - m);
                        acc[COUT] += w;
#pragma unroll
                        for (int o = 0; o < COUT; ++o)
                            acc[o] = fmaf(w, uji_r[j][o], acc[o]);
                    }
                }
                block_sum<COUT + 1>(acc, red, lane, wid);
                float invZ = 1.f / acc[COUT];
#pragma unroll
                for (int o = 0; o < COUT; ++o) s[o] = acc[o] * invZ;
                squash16(s, v);
            }
            float n = 0.f;
#pragma unroll
            for (int o = 0; o < COUT; ++o) n = fmaf(v[o], v[o], n);
            cls0[k] = sqrtf(n);
        }

        // ---------------- Routing for batch 1 (smem u_ji)
        {
            float s[COUT], v[COUT];
#pragma unroll
            for (int o = 0; o < COUT; ++o) s[o] = ss1[o];
            block_sum<COUT>(s, red, lane, wid);
#pragma unroll
            for (int o = 0; o < COUT; ++o) s[o] *= (1.f / RR);
            squash16(s, v);

            float blr[RPT];
            for (int it = 0; it < 2; ++it) {
                float mloc = -1e30f;
#pragma unroll
                for (int j = 0; j < RPT; ++j) {
                    int r = tid + j * NTHREADS;
                    if (r < RR) {
                        float d = 0.f;
#pragma unroll
                        for (int o = 0; o < COUT; ++o)
                            d = fmaf(uji_s[o * RR + r], v[o], d);
                        float nb = (it == 0) ? d : (blr[j] + d);
                        blr[j] = nb;
                        mloc = fmaxf(mloc, nb);
                    }
                }
                float m = block_max(mloc, red, lane, wid);

                float acc[COUT + 1];
#pragma unroll
                for (int o = 0; o <= COUT; ++o) acc[o] = 0.f;
#pragma unroll
                for (int j = 0; j < RPT; ++j) {
                    int r = tid + j * NTHREADS;
                    if (r < RR) {
                        float w = __expf(blr[j] - m);
                        acc[COUT] += w;
#pragma unroll
                        for (int o = 0; o < COUT; ++o)
                            acc[o] = fmaf(w, uji_s[o * RR + r], acc[o]);
                    }
                }
                block_sum<COUT + 1>(acc, red, lane, wid);
                float invZ = 1.f / acc[COUT];
#pragma unroll
                for (int o = 0; o < COUT; ++o) s[o] = acc[o] * invZ;
                squash16(s, v);
            }
            float n = 0.f;
#pragma unroll
            for (int o = 0; o < COUT; ++o) n = fmaf(v[o], v[o], n);
            cls1[k] = sqrtf(n);
        }
        __syncthreads();   // uji_s reuse safety across k (readers done via block_sum syncs; belt+braces)
    }

    // ---------------- final 2-way softmax per batch
    if (tid == 0) {
        {
            float m = fmaxf(cls0[0], cls0[1]);
            float e0 = __expf(cls0[0] - m), e1 = __expf(cls0[1] - m);
            float inv = 1.f / (e0 + e1);
            out[b0 * NK + 0] = e0 * inv;
            out[b0 * NK + 1] = e1 * inv;
        }
        {
            float m = fmaxf(cls1[0], cls1[1]);
            float e0 = __expf(cls1[0] - m), e1 = __expf(cls1[1] - m);
            float inv = 1.f / (e0 + e1);
            out[b1 * NK + 0] = e0 * inv;
            out[b1 * NK + 1] = e1 * inv;
        }
    }
}

extern "C" void kernel_launch(void* const* d_in, const int* in_sizes, int n_in,
                              void* d_out, int out_size) {
    const float* u = (const float*)d_in[0];   // [1024, 2336, 4]
    const float* W = (const float*)d_in[1];   // [2, 2336, 4, 16]
    float* out = (float*)d_out;               // [1024, 2]

    const int wtotal = NK * RR * CIN * COUT;
    wtrans_kernel<<<(wtotal + 255) / 256, 256>>>(W);

    const int smem_bytes = (COUT * RR + NWARP * 17 + 8) * sizeof(float);
    cudaFuncSetAttribute(caps_kernel,
                         cudaFuncAttributeMaxDynamicSharedMemorySize, smem_bytes);
    caps_kernel<<<512, NTHREADS, smem_bytes>>>(u, out);
}